// round 2
// baseline (speedup 1.0000x reference)
#include <cuda_runtime.h>
#include <cstdint>

// ---------------------------------------------------------------------------
// AnisotropicDistance: out[b,i,j] = alpha_i * max(||d||^2 + a^2*(|t_i|^2-2), 0)
//                                 + beta_i * a^2
// where d = p_i - p_j, a = d . t_i.
// B=2, N=8192 -> 537MB fp32 output: DRAM-write bound. Strategy:
//   pack kernel:  per-point float4 (p, |p|^2) + per-row constant float4s
//   main kernel:  4i x 4j register microtile, float4 streaming stores
// ---------------------------------------------------------------------------

#define MAX_BN 32768

__device__ float4 g_pack[MAX_BN];  // (px, py, pz, |p|^2)        -- j-side data
__device__ float4 g_rA[MAX_BN];    // (-tx, -ty, -tz, p.t)       -- i-side
__device__ float4 g_rB[MAX_BN];    // (-2px, -2py, -2pz, |p|^2)  -- i-side
__device__ float4 g_rC[MAX_BN];    // (|t|^2-2, alpha, beta, 0)  -- i-side

__global__ void pack_kernel(const float* __restrict__ pts,
                            const float* __restrict__ pd,
                            const float* __restrict__ lin, int BN) {
    int n = blockIdx.x * blockDim.x + threadIdx.x;
    if (n >= BN) return;
    float px = pts[3 * n + 0], py = pts[3 * n + 1], pz = pts[3 * n + 2];
    float tx = pd[3 * n + 0],  ty = pd[3 * n + 1],  tz = pd[3 * n + 2];
    float l  = lin[n];
    float sq     = fmaf(px, px, fmaf(py, py, pz * pz));
    float tn2    = fmaf(tx, tx, fmaf(ty, ty, tz * tz));
    float pdself = fmaf(px, tx, fmaf(py, ty, pz * tz));
    g_pack[n] = make_float4(px, py, pz, sq);
    g_rA[n]   = make_float4(-tx, -ty, -tz, pdself);
    g_rB[n]   = make_float4(-2.0f * px, -2.0f * py, -2.0f * pz, sq);
    g_rC[n]   = make_float4(tn2 - 2.0f, 2.0f * (1.0f + l), 0.5f * (1.0f - l), 0.0f);
}

constexpr int TI = 4;        // i-rows per block
constexpr int TJ = 4;        // j-cols per thread (one float4 store per row)
constexpr int THREADS = 256; // j-span per block = 1024

__global__ __launch_bounds__(THREADS)
void dist_kernel(float* __restrict__ out, int N) {
    const int b  = blockIdx.z;
    const int i0 = blockIdx.y * TI;
    const int j0 = blockIdx.x * (THREADS * TJ) + threadIdx.x * TJ;
    const int base = b * N;

    // Row constants: uniform addresses across the block -> L1 broadcast.
    float4 A[TI], Bv[TI], C[TI];
#pragma unroll
    for (int ii = 0; ii < TI; ii++) {
        A[ii]  = g_rA[base + i0 + ii];
        Bv[ii] = g_rB[base + i0 + ii];
        C[ii]  = g_rC[base + i0 + ii];
    }

    // j-tile: 4 consecutive float4 loads per thread (64B contiguous).
    float4 pj[TJ];
#pragma unroll
    for (int jj = 0; jj < TJ; jj++) pj[jj] = g_pack[base + j0 + jj];

    const size_t obase = ((size_t)b * N + (size_t)i0) * (size_t)N + (size_t)j0;

#pragma unroll
    for (int ii = 0; ii < TI; ii++) {
        float o[TJ];
#pragma unroll
        for (int jj = 0; jj < TJ; jj++) {
            float4 p = pj[jj];
            // a = p_i.t_i - p_j.t_i  (via -t folded into A)
            float along = fmaf(p.x, A[ii].x,
                          fmaf(p.y, A[ii].y,
                          fmaf(p.z, A[ii].z, A[ii].w)));
            // ||p_i - p_j||^2 = |p_i|^2 + |p_j|^2 - 2 p_i.p_j (via -2p_i in B)
            float sqd = fmaf(p.x, Bv[ii].x,
                        fmaf(p.y, Bv[ii].y,
                        fmaf(p.z, Bv[ii].z, Bv[ii].w + p.w)));
            float a2  = along * along;
            float nrm = fmaxf(fmaf(a2, C[ii].x, sqd), 0.0f);
            o[jj] = fmaf(C[ii].y, nrm, C[ii].z * a2);
        }
        // Streaming store: output is write-once, keep L2 for the j-pack.
        __stcs(reinterpret_cast<float4*>(out + obase + (size_t)ii * N),
               make_float4(o[0], o[1], o[2], o[3]));
    }
}

// Fallback for shapes not divisible by the tile (not expected for N=8192).
__global__ void dist_kernel_generic(float* __restrict__ out, int N, int Btot) {
    int64_t idx = (int64_t)blockIdx.x * blockDim.x + threadIdx.x;
    int64_t total = (int64_t)Btot * N * N;
    if (idx >= total) return;
    int j = (int)(idx % N);
    int64_t t = idx / N;
    int i = (int)(t % N);
    int b = (int)(t / N);
    float4 A  = g_rA[b * N + i];
    float4 Bv = g_rB[b * N + i];
    float4 C  = g_rC[b * N + i];
    float4 p  = g_pack[b * N + j];
    float along = fmaf(p.x, A.x, fmaf(p.y, A.y, fmaf(p.z, A.z, A.w)));
    float sqd   = fmaf(p.x, Bv.x, fmaf(p.y, Bv.y, fmaf(p.z, Bv.z, Bv.w + p.w)));
    float a2    = along * along;
    float nrm   = fmaxf(fmaf(a2, C.x, sqd), 0.0f);
    out[idx]    = fmaf(C.y, nrm, C.z * a2);
}

extern "C" void kernel_launch(void* const* d_in, const int* in_sizes, int n_in,
                              void* d_out, int out_size) {
    const float* points = (const float*)d_in[0];
    const float* pdir   = (const float*)d_in[1];
    const float* lin    = (const float*)d_in[2];
    float* out = (float*)d_out;

    const int BN = in_sizes[2];              // B*N (linearity has 1 elem/point)
    const int N  = (int)((long long)out_size / BN);
    const int B  = BN / N;

    pack_kernel<<<(BN + 255) / 256, 256>>>(points, pdir, lin, BN);

    if ((N % (THREADS * TJ)) == 0 && (N % TI) == 0) {
        dim3 grid(N / (THREADS * TJ), N / TI, B);
        dist_kernel<<<grid, THREADS>>>(out, N);
    } else {
        int64_t total = (int64_t)B * N * N;
        int64_t blocks = (total + 255) / 256;
        dist_kernel_generic<<<(unsigned)blocks, 256>>>(out, N, B);
    }
}

// round 5
// speedup vs baseline: 1.7170x; 1.7170x over previous
#include <cuda_runtime.h>
#include <cstdint>

// ---------------------------------------------------------------------------
// AnisotropicDistance: out[b,i,j] = alpha_i * max(||d||^2 + a^2*(|t_i|^2-2), 0)
//                                 + beta_i * a^2,  d = p_i - p_j, a = d . t_i
// B=2, N=8192 -> 537MB fp32 output: DRAM-write bound.
// R2 fix: transpose thread->column map so g_pack LDG.128 is 16B-stride
// coalesced (was 64B stride -> 16 wavefronts/LDG, L1 @ 80%). TI=16 rows/block
// amortizes the register-resident j-tile 16x; row constants stream via
// uniform broadcast loads inside the row loop (regs 74 -> ~40).
// ---------------------------------------------------------------------------

#define MAX_BN 32768

__device__ float4 g_pack[MAX_BN];  // (px, py, pz, |p|^2)        -- j-side data
__device__ float4 g_rA[MAX_BN];    // (-tx, -ty, -tz, p.t)       -- i-side
__device__ float4 g_rB[MAX_BN];    // (-2px, -2py, -2pz, |p|^2)  -- i-side
__device__ float4 g_rC[MAX_BN];    // (|t|^2-2, alpha, beta, 0)  -- i-side

__global__ void pack_kernel(const float* __restrict__ pts,
                            const float* __restrict__ pd,
                            const float* __restrict__ lin, int BN) {
    int n = blockIdx.x * blockDim.x + threadIdx.x;
    if (n >= BN) return;
    float px = pts[3 * n + 0], py = pts[3 * n + 1], pz = pts[3 * n + 2];
    float tx = pd[3 * n + 0],  ty = pd[3 * n + 1],  tz = pd[3 * n + 2];
    float l  = lin[n];
    float sq     = fmaf(px, px, fmaf(py, py, pz * pz));
    float tn2    = fmaf(tx, tx, fmaf(ty, ty, tz * tz));
    float pdself = fmaf(px, tx, fmaf(py, ty, pz * tz));
    g_pack[n] = make_float4(px, py, pz, sq);
    g_rA[n]   = make_float4(-tx, -ty, -tz, pdself);
    g_rB[n]   = make_float4(-2.0f * px, -2.0f * py, -2.0f * pz, sq);
    g_rC[n]   = make_float4(tn2 - 2.0f, 2.0f * (1.0f + l), 0.5f * (1.0f - l), 0.0f);
}

constexpr int TI      = 16;            // i-rows per block
constexpr int THREADS = 256;
constexpr int TJ      = 4;             // j-cols per thread (strided by THREADS)
constexpr int JSPAN   = THREADS * TJ;  // 1024 cols per block

__global__ __launch_bounds__(THREADS)
void dist_kernel(float* __restrict__ out, int N) {
    const int b    = blockIdx.z;
    const int i0   = blockIdx.y * TI;
    const int j0   = blockIdx.x * JSPAN + threadIdx.x;  // col of lane's slot 0
    const int base = b * N;

    // j-tile: 4 float4 loads, 16B inter-thread stride -> fully coalesced.
    float4 pj[TJ];
#pragma unroll
    for (int jj = 0; jj < TJ; jj++)
        pj[jj] = g_pack[base + j0 + jj * THREADS];

    size_t orow = ((size_t)b * N + (size_t)i0) * (size_t)N + (size_t)j0;

#pragma unroll 4
    for (int ii = 0; ii < TI; ii++) {
        // Uniform address across the block -> L1 broadcast, L2 resident.
        const float4 A  = g_rA[base + i0 + ii];
        const float4 Bv = g_rB[base + i0 + ii];
        const float4 C  = g_rC[base + i0 + ii];
#pragma unroll
        for (int jj = 0; jj < TJ; jj++) {
            const float4 p = pj[jj];
            // a = p_i.t_i - p_j.t_i  (via -t folded into A)
            float along = fmaf(p.x, A.x, fmaf(p.y, A.y, fmaf(p.z, A.z, A.w)));
            // ||p_i - p_j||^2 = |p_i|^2 + |p_j|^2 - 2 p_i.p_j (via -2p_i in B)
            float sqd = fmaf(p.x, Bv.x,
                        fmaf(p.y, Bv.y,
                        fmaf(p.z, Bv.z, Bv.w + p.w)));
            float a2  = along * along;
            float nrm = fmaxf(fmaf(a2, C.x, sqd), 0.0f);
            // Coalesced scalar streaming store (write-once; spare L2).
            __stcs(out + orow + (size_t)jj * THREADS, fmaf(C.y, nrm, C.z * a2));
        }
        orow += N;
    }
}

// Fallback for shapes not divisible by the tile (not expected for N=8192).
__global__ void dist_kernel_generic(float* __restrict__ out, int N, int Btot) {
    int64_t idx = (int64_t)blockIdx.x * blockDim.x + threadIdx.x;
    int64_t total = (int64_t)Btot * N * N;
    if (idx >= total) return;
    int j = (int)(idx % N);
    int64_t t = idx / N;
    int i = (int)(t % N);
    int b = (int)(t / N);
    float4 A  = g_rA[b * N + i];
    float4 Bv = g_rB[b * N + i];
    float4 C  = g_rC[b * N + i];
    float4 p  = g_pack[b * N + j];
    float along = fmaf(p.x, A.x, fmaf(p.y, A.y, fmaf(p.z, A.z, A.w)));
    float sqd   = fmaf(p.x, Bv.x, fmaf(p.y, Bv.y, fmaf(p.z, Bv.z, Bv.w + p.w)));
    float a2    = along * along;
    float nrm   = fmaxf(fmaf(a2, C.x, sqd), 0.0f);
    out[idx]    = fmaf(C.y, nrm, C.z * a2);
}

extern "C" void kernel_launch(void* const* d_in, const int* in_sizes, int n_in,
                              void* d_out, int out_size) {
    const float* points = (const float*)d_in[0];
    const float* pdir   = (const float*)d_in[1];
    const float* lin    = (const float*)d_in[2];
    float* out = (float*)d_out;

    const int BN = in_sizes[2];              // B*N (linearity has 1 elem/point)
    const int N  = (int)((long long)out_size / BN);
    const int B  = BN / N;

    pack_kernel<<<(BN + 255) / 256, 256>>>(points, pdir, lin, BN);

    if ((N % JSPAN) == 0 && (N % TI) == 0) {
        dim3 grid(N / JSPAN, N / TI, B);
        dist_kernel<<<grid, THREADS>>>(out, N);
    } else {
        int64_t total = (int64_t)B * N * N;
        int64_t blocks = (total + 255) / 256;
        dist_kernel_generic<<<(unsigned)blocks, 256>>>(out, N, B);
    }
}